// round 13
// baseline (speedup 1.0000x reference)
#include <cuda_runtime.h>
#include <cuda_pipeline.h>
#include <cstdint>

#define NN 1000
#define D 128
#define STR 384      // K_att/V_att innermost stride in floats (3 * 128)
#define SEG 125      // nodes per CTA segment (8 CTAs per batch)
#define CAP 64       // cached unmasked nodes per CTA (smem capacity)
#define NW 8         // warps per CTA
#define THREADS 256
#define CL 8         // cluster size

struct Smem {
    float kc1[CAP][D];   // K[128:256) cache (layer 1)
    float kc2[CAP][D];   // K[256:384) cache (layer 2)
    float vc1[CAP][D];   // V[128:256) cache (layer 1)
    float qs[D];
    float mo[D];
    float m_s[NW][32];
    float l_s[NW][32];
    float4 a_s[NW][32];
    float xbuf[32][6];   // cluster merge: m,l,acc4 per lane
    float x2[2];         // cluster merge: layer-2 scalar stats
    float fin[2];        // final M, 1/L (layer 2)
    float ss[SEG];       // staged layer-2 logits (local index)
    unsigned short nlist[SEG + 3];
    int cnt;
};

__device__ __forceinline__ float4 zero4() { return make_float4(0.f, 0.f, 0.f, 0.f); }

__device__ __forceinline__ uint32_t smem_u32(const void* p) {
    uint32_t a;
    asm("{ .reg .u64 t; cvta.to.shared.u64 t, %1; cvt.u32.u64 %0, t; }" : "=r"(a) : "l"(p));
    return a;
}
__device__ __forceinline__ float dsmem_ld(uint32_t laddr, uint32_t rank) {
    uint32_t ra; float v;
    asm volatile("mapa.shared::cluster.u32 %0, %1, %2;" : "=r"(ra) : "r"(laddr), "r"(rank));
    asm volatile("ld.shared::cluster.f32 %0, [%1];" : "=f"(v) : "r"(ra) : "memory");
    return v;
}
#define CLUSTER_SYNC() do { \
    asm volatile("barrier.cluster.arrive.aligned;" ::: "memory"); \
    asm volatile("barrier.cluster.wait.aligned;" ::: "memory"); } while (0)

extern __shared__ char smem_raw[];

// 8-CTA cluster per batch (125 nodes/CTA). Phase A: stream each unmasked
// node's CONTIGUOUS 2.5KB span (K row 1536B + V 1024B), computing layer 0
// online; layer-1/2 slices land directly in smem via cp.async. Phases B/C run
// from smem. Softmax merges across the cluster via DSMEM + cluster syncs.

__global__ void __cluster_dims__(CL, 1, 1) __launch_bounds__(THREADS, 2)
decoder_cluster_kernel(
    const float* __restrict__ query,
    const float* __restrict__ K_att,
    const float* __restrict__ V_att,
    const int* __restrict__ mask,          // bool serialized as int32
    const float* __restrict__ W0_w,
    const float* __restrict__ W0_b,
    const float* __restrict__ Wq_w,
    const float* __restrict__ Wq_b,
    float* __restrict__ out)
{
    Smem* S = (Smem*)smem_raw;
    const int b    = blockIdx.x / CL;
    const int rank = blockIdx.x % CL;
    const int seg0 = rank * SEG;
    const int tid  = threadIdx.x;
    const int wid  = tid >> 5;
    const int lane = tid & 31;
    const int loff = 4 * lane;

    if (tid < D) S->qs[tid] = query[(size_t)b * D + tid];

    // ---- compact unmasked nodes of this segment (warp 0), local indices ----
    const int* mrow = mask + (size_t)b * NN;
    if (wid == 0) {
        int base = 0;
        for (int start = 0; start < SEG; start += 32) {
            int n = start + lane;
            bool keep = (n < SEG) && (mrow[seg0 + n] == 0);
            unsigned bal = __ballot_sync(0xffffffffu, keep);
            if (keep) S->nlist[base + __popc(bal & ((1u << lane) - 1u))] = (unsigned short)n;
            base += __popc(bal);
        }
        if (lane == 0) S->cnt = base;
    }
    __syncthreads();
    const int cnt = S->cnt;

    const float* Kb = K_att + (size_t)b * NN * STR;
    const float* Vb = V_att + (size_t)b * NN * STR;

    // ==================== Phase A: layer 0 + contiguous-span streaming ====================
    {
        const float4 q4 = *(const float4*)(S->qs + loff);
        float m = -1e30f, lsum = 0.f;
        float4 acc = zero4();

        // issue all requests of node i back-to-back (2.5KB near-contiguous span)
        auto issueA = [&](int i, float4& k0, float4& v0) {
            const size_t ro = (size_t)(seg0 + S->nlist[i]) * STR;
            k0 = *(const float4*)(Kb + ro + loff);                 // K[0:512)
            if (i < CAP) {
                __pipeline_memcpy_async(&S->kc1[i][loff], Kb + ro + D + loff, 16);
                __pipeline_memcpy_async(&S->kc2[i][loff], Kb + ro + 2 * D + loff, 16);
            }
            v0 = *(const float4*)(Vb + ro + loff);                 // V[0:512)
            if (i < CAP)
                __pipeline_memcpy_async(&S->vc1[i][loff], Vb + ro + D + loff, 16);
            __pipeline_commit();                                   // bounded depth
        };

        int i = wid;
        float4 nk0 = zero4(), nv0 = zero4();
        if (i < cnt) issueA(i, nk0, nv0);
        while (i < cnt) {
            const float4 k0 = nk0, v0 = nv0;
            const int in = i + NW;
            if (in < cnt) issueA(in, nk0, nv0);

            float s = k0.x * q4.x + k0.y * q4.y + k0.z * q4.z + k0.w * q4.w;
            s += __shfl_xor_sync(0xffffffffu, s, 1);
            s += __shfl_xor_sync(0xffffffffu, s, 2);
            s *= 0.25f;                                            // 1/sqrt(16)

            const float mn = fmaxf(m, s);
            const float c = __expf(m - mn);
            const float e = __expf(s - mn);
            lsum = lsum * c + e;
            acc.x = acc.x * c + e * v0.x;
            acc.y = acc.y * c + e * v0.y;
            acc.z = acc.z * c + e * v0.z;
            acc.w = acc.w * c + e * v0.w;
            m = mn;
            i = in;
        }
        __pipeline_commit();
        __pipeline_wait_prior(0);   // this thread's cache slices landed

        S->m_s[wid][lane] = m; S->l_s[wid][lane] = lsum; S->a_s[wid][lane] = acc;
    }
    __syncthreads();

    // local merge -> publish CTA partial
    if (tid < 32) {
        float M = S->m_s[0][lane];
        #pragma unroll
        for (int w = 1; w < NW; ++w) M = fmaxf(M, S->m_s[w][lane]);
        float L = 0.f, ax = 0.f, ay = 0.f, az = 0.f, aw = 0.f;
        #pragma unroll
        for (int w = 0; w < NW; ++w) {
            const float c = __expf(S->m_s[w][lane] - M);
            L += S->l_s[w][lane] * c;
            const float4 a = S->a_s[w][lane];
            ax += a.x * c; ay += a.y * c; az += a.z * c; aw += a.w * c;
        }
        S->xbuf[lane][0] = M; S->xbuf[lane][1] = L;
        S->xbuf[lane][2] = ax; S->xbuf[lane][3] = ay;
        S->xbuf[lane][4] = az; S->xbuf[lane][5] = aw;
    }
    CLUSTER_SYNC();   // CS1: partials published
    if (tid < 32) {
        const uint32_t bx = smem_u32(&S->xbuf[lane][0]);
        float M = -1e30f;
        float mr[CL], lr[CL], a0[CL], a1[CL], a2[CL], a3[CL];
        #pragma unroll
        for (int r = 0; r < CL; ++r) {
            mr[r] = dsmem_ld(bx +  0, r); lr[r] = dsmem_ld(bx +  4, r);
            a0[r] = dsmem_ld(bx +  8, r); a1[r] = dsmem_ld(bx + 12, r);
            a2[r] = dsmem_ld(bx + 16, r); a3[r] = dsmem_ld(bx + 20, r);
            M = fmaxf(M, mr[r]);
        }
        float L = 0.f, ax = 0.f, ay = 0.f, az = 0.f, aw = 0.f;
        #pragma unroll
        for (int r = 0; r < CL; ++r) {
            const float c = __expf(mr[r] - M);
            L += lr[r] * c;
            ax += a0[r] * c; ay += a1[r] * c; az += a2[r] * c; aw += a3[r] * c;
        }
        const float inv = 1.0f / L;
        S->mo[loff + 0] = ax * inv; S->mo[loff + 1] = ay * inv;
        S->mo[loff + 2] = az * inv; S->mo[loff + 3] = aw * inv;
    }
    CLUSTER_SYNC();   // CS2: xbuf reads done everywhere (safe to overwrite)
    if (tid < D) {    // query = out0 @ W0.T + b0
        const float* Wr = W0_w + tid * D;
        float a2 = W0_b[tid];
        #pragma unroll 8
        for (int d = 0; d < D; ++d) a2 = fmaf(S->mo[d], Wr[d], a2);
        S->qs[tid] = a2;
    }
    __syncthreads();

    // ==================== Phase B: layer 1 from smem cache ====================
    {
        const float4 q4 = *(const float4*)(S->qs + loff);
        float m = -1e30f, lsum = 0.f;
        float4 acc = zero4();
        for (int i = wid; i < cnt; i += NW) {
            float4 k4, v4;
            if (i < CAP) {
                k4 = *(const float4*)&S->kc1[i][loff];
                v4 = *(const float4*)&S->vc1[i][loff];
            } else {
                const size_t ro = (size_t)(seg0 + S->nlist[i]) * STR;
                k4 = *(const float4*)(Kb + ro + D + loff);
                v4 = *(const float4*)(Vb + ro + D + loff);
            }
            float s = k4.x * q4.x + k4.y * q4.y + k4.z * q4.z + k4.w * q4.w;
            s += __shfl_xor_sync(0xffffffffu, s, 1);
            s += __shfl_xor_sync(0xffffffffu, s, 2);
            s *= 0.25f;
            const float mn = fmaxf(m, s);
            const float c = __expf(m - mn);
            const float e = __expf(s - mn);
            lsum = lsum * c + e;
            acc.x = acc.x * c + e * v4.x;
            acc.y = acc.y * c + e * v4.y;
            acc.z = acc.z * c + e * v4.z;
            acc.w = acc.w * c + e * v4.w;
            m = mn;
        }
        S->m_s[wid][lane] = m; S->l_s[wid][lane] = lsum; S->a_s[wid][lane] = acc;
    }
    __syncthreads();
    if (tid < 32) {
        float M = S->m_s[0][lane];
        #pragma unroll
        for (int w = 1; w < NW; ++w) M = fmaxf(M, S->m_s[w][lane]);
        float L = 0.f, ax = 0.f, ay = 0.f, az = 0.f, aw = 0.f;
        #pragma unroll
        for (int w = 0; w < NW; ++w) {
            const float c = __expf(S->m_s[w][lane] - M);
            L += S->l_s[w][lane] * c;
            const float4 a = S->a_s[w][lane];
            ax += a.x * c; ay += a.y * c; az += a.z * c; aw += a.w * c;
        }
        S->xbuf[lane][0] = M; S->xbuf[lane][1] = L;
        S->xbuf[lane][2] = ax; S->xbuf[lane][3] = ay;
        S->xbuf[lane][4] = az; S->xbuf[lane][5] = aw;
    }
    CLUSTER_SYNC();   // CS3
    if (tid < 32) {
        const uint32_t bx = smem_u32(&S->xbuf[lane][0]);
        float M = -1e30f;
        float mr[CL], lr[CL], a0[CL], a1[CL], a2[CL], a3[CL];
        #pragma unroll
        for (int r = 0; r < CL; ++r) {
            mr[r] = dsmem_ld(bx +  0, r); lr[r] = dsmem_ld(bx +  4, r);
            a0[r] = dsmem_ld(bx +  8, r); a1[r] = dsmem_ld(bx + 12, r);
            a2[r] = dsmem_ld(bx + 16, r); a3[r] = dsmem_ld(bx + 20, r);
            M = fmaxf(M, mr[r]);
        }
        float L = 0.f, ax = 0.f, ay = 0.f, az = 0.f, aw = 0.f;
        #pragma unroll
        for (int r = 0; r < CL; ++r) {
            const float c = __expf(mr[r] - M);
            L += lr[r] * c;
            ax += a0[r] * c; ay += a1[r] * c; az += a2[r] * c; aw += a3[r] * c;
        }
        const float inv = 1.0f / L;
        S->mo[loff + 0] = ax * inv; S->mo[loff + 1] = ay * inv;
        S->mo[loff + 2] = az * inv; S->mo[loff + 3] = aw * inv;
    }
    CLUSTER_SYNC();   // CS4
    if (tid < D) {    // query = out1 @ W0.T + b0
        const float* Wr = W0_w + tid * D;
        float a2 = W0_b[tid];
        #pragma unroll 8
        for (int d = 0; d < D; ++d) a2 = fmaf(S->mo[d], Wr[d], a2);
        S->qs[tid] = a2;
    }
    __syncthreads();
    if (tid < D) {    // q_final = query @ Wq.T + bq
        const float* Wr = Wq_w + tid * D;
        float a2 = Wq_b[tid];
        #pragma unroll 8
        for (int d = 0; d < D; ++d) a2 = fmaf(S->qs[d], Wr[d], a2);
        S->mo[tid] = a2;
    }
    __syncthreads();

    // ==================== Phase C: layer 2 (1 head, clip 10) from smem ====================
    {
        const float4 q4 = *(const float4*)(S->mo + loff);
        float m = -1e30f, lsum = 0.f;
        for (int i = wid; i < cnt; i += NW) {
            float4 k4;
            if (i < CAP) k4 = *(const float4*)&S->kc2[i][loff];
            else k4 = *(const float4*)(Kb + (size_t)(seg0 + S->nlist[i]) * STR + 2 * D + loff);

            float s = k4.x * q4.x + k4.y * q4.y + k4.z * q4.z + k4.w * q4.w;
            #pragma unroll
            for (int d = 1; d < 32; d <<= 1)
                s += __shfl_xor_sync(0xffffffffu, s, d);
            s *= 0.08838834764831845f;   // 1/sqrt(128)
            s = 10.0f * (1.0f - __fdividef(2.0f, __expf(2.0f * s) + 1.0f));  // 10*tanh

            if (lane == 0) S->ss[i] = s;
            const float mn = fmaxf(m, s);
            lsum = lsum * __expf(m - mn) + __expf(s - mn);
            m = mn;
        }
        if (lane == 0) { S->m_s[wid][0] = m; S->l_s[wid][0] = lsum; }
    }
    __syncthreads();
    if (tid == 0) {
        float M = S->m_s[0][0];
        #pragma unroll
        for (int w = 1; w < NW; ++w) M = fmaxf(M, S->m_s[w][0]);
        float L = 0.f;
        #pragma unroll
        for (int w = 0; w < NW; ++w) L += S->l_s[w][0] * __expf(S->m_s[w][0] - M);
        S->x2[0] = M; S->x2[1] = L;
    }
    CLUSTER_SYNC();   // CS5: scalar stats published
    if (tid == 0) {
        const uint32_t bx = smem_u32(&S->x2[0]);
        float M = -1e30f;
        float mr[CL], lr[CL];
        #pragma unroll
        for (int r = 0; r < CL; ++r) {
            mr[r] = dsmem_ld(bx, r); lr[r] = dsmem_ld(bx + 4, r);
            M = fmaxf(M, mr[r]);
        }
        float L = 0.f;
        #pragma unroll
        for (int r = 0; r < CL; ++r) L += lr[r] * __expf(mr[r] - M);
        S->fin[0] = M; S->fin[1] = 1.0f / L;
    }
    CLUSTER_SYNC();   // CS6: ALL remote x2 reads complete before any CTA may exit

    {
        const float M = S->fin[0], Li = S->fin[1];
        float* orow = out + (size_t)b * NN + seg0;
        for (int n = tid; n < SEG; n += THREADS) orow[n] = 0.0f;
        __syncthreads();
        for (int i = tid; i < cnt; i += THREADS)
            orow[S->nlist[i]] = __expf(S->ss[i] - M) * Li;
    }
}

extern "C" void kernel_launch(void* const* d_in, const int* in_sizes, int n_in,
                              void* d_out, int out_size) {
    const float* query = (const float*)d_in[0];
    const float* K_att = (const float*)d_in[1];
    const float* V_att = (const float*)d_in[2];
    const int*   mask  = (const int*)d_in[3];
    const float* W0_w  = (const float*)d_in[4];
    const float* W0_b  = (const float*)d_in[5];
    const float* Wq_w  = (const float*)d_in[6];
    const float* Wq_b  = (const float*)d_in[7];
    float* out = (float*)d_out;

    const int smem_bytes = (int)sizeof(Smem);
    cudaFuncSetAttribute(decoder_cluster_kernel,
                         cudaFuncAttributeMaxDynamicSharedMemorySize, smem_bytes);
    decoder_cluster_kernel<<<512 * CL, THREADS, smem_bytes>>>(
        query, K_att, V_att, mask, W0_w, W0_b, Wq_w, Wq_b, out);
}

// round 14
// speedup vs baseline: 5.1556x; 5.1556x over previous
#include <cuda_runtime.h>
#include <cuda_pipeline.h>
#include <cstdint>

#define NN 1000
#define D 128
#define STR 384      // K_att/V_att innermost stride in floats (3 * 128)
#define NW 8         // warps per CTA
#define CH 3         // adjacent nodes per chunk (row-locality unit)
#define DEPTH 2      // double buffer

__device__ __forceinline__ float4 zero4() { return make_float4(0.f, 0.f, 0.f, 0.f); }

// One CTA per batch, 8 warps, occupancy 4 (single wave of 512 CTAs).
// R8 winning config: round-robin CH=3 chunks, cp.async double buffer,
// interleaved K/V issue. Added: parallel 8-warp compaction, smem logit
// staging epilogue (no gmem logit round-trip).

__global__ __launch_bounds__(256, 4)
void decoder_fused_kernel(
    const float* __restrict__ query,
    const float* __restrict__ K_att,
    const float* __restrict__ V_att,
    const int* __restrict__ mask,          // bool serialized as int32
    const float* __restrict__ W0_w,
    const float* __restrict__ W0_b,
    const float* __restrict__ Wq_w,
    const float* __restrict__ Wq_b,
    float* __restrict__ out)
{
    __shared__ __align__(16) float ring[NW * DEPTH * CH * 256];  // 48 KB
    __shared__ unsigned short nlist[NN];                          // 2 KB
    __shared__ float ss[NN];                                      // 4 KB staged logits
    __shared__ int wcnt[NW + 1];
    __shared__ __align__(16) float qs[D];
    __shared__ __align__(16) float mo[D];
    __shared__ float M2s, L2s;

    // merge scratch aliased onto ring (dead between layer loops)
    float*  m_s = ring;                   // [NW][32]
    float*  l_s = ring + 256;             // [NW][32]
    float4* a_s = (float4*)(ring + 512);  // [NW][32]

    const int b = blockIdx.x;
    const int tid = threadIdx.x;
    const int wid = tid >> 5;
    const int lane = tid & 31;
    const int loff = 4 * lane;
    const float NEG = __int_as_float(0xff800000);  // -inf

    if (tid < D) qs[tid] = query[(size_t)b * D + tid];

    // ---- Parallel compaction: warp w scans nodes [125w, 125(w+1)) ----
    const int* mrow = mask + (size_t)b * NN;
    {
        const int s0 = wid * 125;
        // pass 1: count
        int cnt_w = 0;
        for (int start = s0; start < s0 + 125; start += 32) {
            int n = start + lane;
            bool keep = (n < s0 + 125) && (mrow[n] == 0);
            cnt_w += __popc(__ballot_sync(0xffffffffu, keep));
        }
        if (lane == 0) wcnt[wid] = cnt_w;
        __syncthreads();
        // prefix (warp 0, tiny)
        if (tid == 0) {
            int acc = 0;
            #pragma unroll
            for (int w = 0; w < NW; ++w) { int t = wcnt[w]; wcnt[w] = acc; acc += t; }
            wcnt[NW] = acc;
        }
        __syncthreads();
        // pass 2: scatter
        int base = wcnt[wid];
        for (int start = s0; start < s0 + 125; start += 32) {
            int n = start + lane;
            bool keep = (n < s0 + 125) && (mrow[n] == 0);
            unsigned bal = __ballot_sync(0xffffffffu, keep);
            if (keep) nlist[base + __popc(bal & ((1u << lane) - 1u))] = (unsigned short)n;
            base += __popc(bal);
        }
    }
    __syncthreads();
    const int cnt = wcnt[NW];
    const int nch = (cnt + CH - 1) / CH;

    const float* Kb = K_att + (size_t)b * NN * STR;
    const float* Vb = V_att + (size_t)b * NN * STR;
    float* rw = ring + wid * (DEPTH * CH * 256);

    // ==================== Layers 0 and 1 ====================
    for (int l = 0; l < 2; ++l) {
        const int cbase = l * D + loff;

        // prologue: fill both buffers (chunks w, w+NW), interleaved K/V per node
        #pragma unroll
        for (int d = 0; d < DEPTH; ++d) {
            const int c = wid + d * NW;
            float* buf = rw + d * (CH * 256);
            if (c < nch) {
                #pragma unroll
                for (int j = 0; j < CH; ++j) {
                    int i = c * CH + j;
                    int node = nlist[i < cnt ? i : 0];
                    size_t o = (size_t)node * STR + cbase;
                    __pipeline_memcpy_async(buf + j * 256 + loff, Kb + o, 16);
                    __pipeline_memcpy_async(buf + j * 256 + 128 + loff, Vb + o, 16);
                }
            }
            __pipeline_commit();
        }

        const float4 q4 = *(const float4*)(qs + loff);
        float m = -1e30f, lsum = 0.0f;
        float4 acc = zero4();

        int it = 0;
        for (int c = wid; c < nch; c += NW, ++it) {
            __pipeline_wait_prior(1);
            float* buf = rw + (it & 1) * (CH * 256);

            #pragma unroll
            for (int j = 0; j < CH; ++j) {
                const float4 k4 = *(const float4*)(buf + j * 256 + loff);
                const float4 v4 = *(const float4*)(buf + j * 256 + 128 + loff);
                float s = k4.x * q4.x + k4.y * q4.y + k4.z * q4.z + k4.w * q4.w;
                s += __shfl_xor_sync(0xffffffffu, s, 1);
                s += __shfl_xor_sync(0xffffffffu, s, 2);
                s = (c * CH + j < cnt) ? s * 0.25f : NEG;  // 1/sqrt(16)

                const float mn = fmaxf(m, s);
                const float cc = __expf(m - mn);
                const float e = __expf(s - mn);     // 0 for padded slots
                lsum = lsum * cc + e;
                acc.x = acc.x * cc + e * v4.x;
                acc.y = acc.y * cc + e * v4.y;
                acc.z = acc.z * cc + e * v4.z;
                acc.w = acc.w * cc + e * v4.w;
                m = mn;
            }

            const int cn = c + 2 * NW;
            if (cn < nch) {
                #pragma unroll
                for (int j = 0; j < CH; ++j) {
                    int i = cn * CH + j;
                    int node = nlist[i < cnt ? i : 0];
                    size_t o = (size_t)node * STR + cbase;
                    __pipeline_memcpy_async(buf + j * 256 + loff, Kb + o, 16);
                    __pipeline_memcpy_async(buf + j * 256 + 128 + loff, Vb + o, 16);
                }
            }
            __pipeline_commit();
        }
        __pipeline_wait_prior(0);
        __syncthreads();   // ring now dead -> merge scratch

        m_s[wid * 32 + lane] = m;
        l_s[wid * 32 + lane] = lsum;
        a_s[wid * 32 + lane] = acc;
        __syncthreads();

        if (tid < 32) {
            float M = m_s[lane];
            #pragma unroll
            for (int w = 1; w < NW; ++w) M = fmaxf(M, m_s[w * 32 + lane]);
            float L = 0.f, ax = 0.f, ay = 0.f, az = 0.f, aw = 0.f;
            #pragma unroll
            for (int w = 0; w < NW; ++w) {
                const float cc = __expf(m_s[w * 32 + lane] - M);
                L += l_s[w * 32 + lane] * cc;
                const float4 a = a_s[w * 32 + lane];
                ax += a.x * cc; ay += a.y * cc; az += a.z * cc; aw += a.w * cc;
            }
            const float inv = 1.0f / L;
            mo[4 * lane + 0] = ax * inv;
            mo[4 * lane + 1] = ay * inv;
            mo[4 * lane + 2] = az * inv;
            mo[4 * lane + 3] = aw * inv;
        }
        __syncthreads();

        if (tid < D) {   // query = mha_out @ W0_w.T + W0_b
            const float* Wr = W0_w + tid * D;
            float a2 = W0_b[tid];
            #pragma unroll 8
            for (int d = 0; d < D; ++d) a2 = fmaf(mo[d], Wr[d], a2);
            qs[tid] = a2;
        }
        __syncthreads();
    }

    // ==================== Layer 2: q_final = q @ Wq.T + b; 1-head, clip=10 ====================
    if (tid < D) {
        const float* Wr = Wq_w + tid * D;
        float a2 = Wq_b[tid];
        #pragma unroll 8
        for (int d = 0; d < D; ++d) a2 = fmaf(qs[d], Wr[d], a2);
        mo[tid] = a2;
    }
    __syncthreads();

    {
        const int cbase = 2 * D + loff;
        const float4 q4 = *(const float4*)(mo + loff);

        // K-only ring: slot = ring[w][buf][j][0:128]
        #pragma unroll
        for (int d = 0; d < DEPTH; ++d) {
            const int c = wid + d * NW;
            float* buf = rw + d * (CH * 256);
            if (c < nch) {
                #pragma unroll
                for (int j = 0; j < CH; ++j) {
                    int i = c * CH + j;
                    int node = nlist[i < cnt ? i : 0];
                    __pipeline_memcpy_async(buf + j * 256 + loff,
                                            Kb + (size_t)node * STR + cbase, 16);
                }
            }
            __pipeline_commit();
        }

        float m = -1e30f, lsum = 0.0f;
        int it = 0;
        for (int c = wid; c < nch; c += NW, ++it) {
            __pipeline_wait_prior(1);
            float* buf = rw + (it & 1) * (CH * 256);

            #pragma unroll
            for (int j = 0; j < CH; ++j) {
                const int i = c * CH + j;
                const float4 k4 = *(const float4*)(buf + j * 256 + loff);
                float s = k4.x * q4.x + k4.y * q4.y + k4.z * q4.z + k4.w * q4.w;
                #pragma unroll
                for (int d = 1; d < 32; d <<= 1)
                    s += __shfl_xor_sync(0xffffffffu, s, d);
                s *= 0.08838834764831845f;  // 1/sqrt(128)
                s = 10.0f * (1.0f - __fdividef(2.0f, __expf(2.0f * s) + 1.0f));  // 10*tanh
                if (i < cnt) {
                    if (lane == 0) ss[i] = s;   // stage logit in smem
                } else s = NEG;
                const float mn = fmaxf(m, s);
                lsum = lsum * __expf(m - mn) + __expf(s - mn);
                m = mn;
            }

            const int cn = c + 2 * NW;
            if (cn < nch) {
                #pragma unroll
                for (int j = 0; j < CH; ++j) {
                    int i = cn * CH + j;
                    int node = nlist[i < cnt ? i : 0];
                    __pipeline_memcpy_async(buf + j * 256 + loff,
                                            Kb + (size_t)node * STR + cbase, 16);
                }
            }
            __pipeline_commit();
        }
        __pipeline_wait_prior(0);
        __syncthreads();

        if (lane == 0) { m_s[wid * 32] = m; l_s[wid * 32] = lsum; }
        __syncthreads();
        if (tid == 0) {
            float M = m_s[0];
            #pragma unroll
            for (int w = 1; w < NW; ++w) M = fmaxf(M, m_s[w * 32]);
            float L = 0.f;
            #pragma unroll
            for (int w = 0; w < NW; ++w) L += l_s[w * 32] * __expf(m_s[w * 32] - M);
            M2s = M;
            L2s = 1.0f / L;
        }
        __syncthreads();

        // epilogue: zero the row, then scatter normalized weights from smem
        const float M = M2s, Li = L2s;
        float* orow = out + (size_t)b * NN;
        for (int n = tid; n < NN; n += 256) orow[n] = 0.0f;
        __syncthreads();
        for (int i = tid; i < cnt; i += 256)
            orow[nlist[i]] = __expf(ss[i] - M) * Li;
    }
}

extern "C" void kernel_launch(void* const* d_in, const int* in_sizes, int n_in,
                              void* d_out, int out_size) {
    const float* query = (const float*)d_in[0];
    const float* K_att = (const float*)d_in[1];
    const float* V_att = (const float*)d_in[2];
    const int*   mask  = (const int*)d_in[3];
    const float* W0_w  = (const float*)d_in[4];
    const float* W0_b  = (const float*)d_in[5];
    const float* Wq_w  = (const float*)d_in[6];
    const float* Wq_b  = (const float*)d_in[7];
    float* out = (float*)d_out;

    decoder_fused_kernel<<<512, 256>>>(query, K_att, V_att, mask,
                                       W0_w, W0_b, Wq_w, Wq_b, out);
}

// round 15
// speedup vs baseline: 5.1954x; 1.0077x over previous
#include <cuda_runtime.h>
#include <cuda_pipeline.h>
#include <cstdint>

#define NN 1000
#define D 128
#define STR 384      // K_att/V_att innermost stride in floats (3 * 128)
#define NW 8         // warps per CTA
#define CH 3         // adjacent nodes per chunk, layers 0/1 (K+V)
#define CH2 6        // adjacent nodes per chunk, layer 2 (K only)

__device__ __forceinline__ float4 zero4() { return make_float4(0.f, 0.f, 0.f, 0.f); }

// One CTA per batch, 8 warps, occupancy 4 (single wave of 512 CTAs).
// R14 winner + cross-layer prologue overlap: merge scratch aliases warp 0's
// ring buffers only, so warps 1..7 issue the NEXT layer's prologue cp.asyncs
// during the merge/matmul of the current layer (hides the DRAM cold start at
// each layer boundary); warp 0 stages after the scratch is dead.
// Layer 2 packs 6 K-slices per buffer (full slot use, longer adjacent runs).

__global__ __launch_bounds__(256, 4)
void decoder_fused_kernel(
    const float* __restrict__ query,
    const float* __restrict__ K_att,
    const float* __restrict__ V_att,
    const int* __restrict__ mask,          // bool serialized as int32
    const float* __restrict__ W0_w,
    const float* __restrict__ W0_b,
    const float* __restrict__ Wq_w,
    const float* __restrict__ Wq_b,
    float* __restrict__ out)
{
    __shared__ __align__(16) float ring[NW * 2 * CH * 256];  // 48 KB
    __shared__ unsigned short nlist[NN];                      // 2 KB
    __shared__ float ss[NN];                                  // 4 KB staged logits
    __shared__ int wcnt[NW + 1];
    __shared__ __align__(16) float qs[D];
    __shared__ __align__(16) float mo[D];
    __shared__ float M2s, L2s;

    // merge scratch aliased on warp 0's ring area (ring[0..1536))
    float*  m_s = ring;                   // [NW][32]
    float*  l_s = ring + 256;             // [NW][32]
    float4* a_s = (float4*)(ring + 512);  // [NW][32]

    const int b = blockIdx.x;
    const int tid = threadIdx.x;
    const int wid = tid >> 5;
    const int lane = tid & 31;
    const int loff = 4 * lane;
    const float NEG = __int_as_float(0xff800000);  // -inf

    if (tid < D) qs[tid] = query[(size_t)b * D + tid];

    // ---- Parallel compaction: warp w scans nodes [125w, 125(w+1)) ----
    const int* mrow = mask + (size_t)b * NN;
    {
        const int s0 = wid * 125;
        int cnt_w = 0;
        for (int start = s0; start < s0 + 125; start += 32) {
            int n = start + lane;
            bool keep = (n < s0 + 125) && (mrow[n] == 0);
            cnt_w += __popc(__ballot_sync(0xffffffffu, keep));
        }
        if (lane == 0) wcnt[wid] = cnt_w;
        __syncthreads();
        if (tid == 0) {
            int acc = 0;
            #pragma unroll
            for (int w = 0; w < NW; ++w) { int t = wcnt[w]; wcnt[w] = acc; acc += t; }
            wcnt[NW] = acc;
        }
        __syncthreads();
        int base = wcnt[wid];
        for (int start = s0; start < s0 + 125; start += 32) {
            int n = start + lane;
            bool keep = (n < s0 + 125) && (mrow[n] == 0);
            unsigned bal = __ballot_sync(0xffffffffu, keep);
            if (keep) nlist[base + __popc(bal & ((1u << lane) - 1u))] = (unsigned short)n;
            base += __popc(bal);
        }
    }
    __syncthreads();
    const int cnt  = wcnt[NW];
    const int nch  = (cnt + CH - 1) / CH;
    const int nch2 = (cnt + CH2 - 1) / CH2;

    const float* Kb = K_att + (size_t)b * NN * STR;
    const float* Vb = V_att + (size_t)b * NN * STR;
    float* rw = ring + wid * (2 * CH * 256);

    // stage CH nodes (K+V) of layer l, chunk c, into buf; always 1 commit
    auto stageKV = [&](int l, int c, float* buf) {
        if (c < nch) {
            const int cbase = l * D + loff;
            #pragma unroll
            for (int j = 0; j < CH; ++j) {
                int i = c * CH + j;
                int node = nlist[i < cnt ? i : 0];
                size_t o = (size_t)node * STR + cbase;
                __pipeline_memcpy_async(buf + j * 256 + loff, Kb + o, 16);
                __pipeline_memcpy_async(buf + j * 256 + 128 + loff, Vb + o, 16);
            }
        }
        __pipeline_commit();
    };
    // stage CH2 nodes (K only, layer 2) of chunk c into buf; always 1 commit
    auto stageK2 = [&](int c, float* buf) {
        if (c < nch2) {
            const int cbase = 2 * D + loff;
            #pragma unroll
            for (int j = 0; j < CH2; ++j) {
                int i = c * CH2 + j;
                int node = nlist[i < cnt ? i : 0];
                __pipeline_memcpy_async(buf + j * 128 + loff,
                                        Kb + (size_t)node * STR + cbase, 16);
            }
        }
        __pipeline_commit();
    };
    // consume CH nodes of a K+V buffer into flash state
    auto consumeKV = [&](const float* buf, int c, const float4 q4,
                         float& m, float& lsum, float4& acc) {
        #pragma unroll
        for (int j = 0; j < CH; ++j) {
            const float4 k4 = *(const float4*)(buf + j * 256 + loff);
            const float4 v4 = *(const float4*)(buf + j * 256 + 128 + loff);
            float s = k4.x * q4.x + k4.y * q4.y + k4.z * q4.z + k4.w * q4.w;
            s += __shfl_xor_sync(0xffffffffu, s, 1);
            s += __shfl_xor_sync(0xffffffffu, s, 2);
            s = (c * CH + j < cnt) ? s * 0.25f : NEG;   // 1/sqrt(16)
            const float mn = fmaxf(m, s);
            const float cc = __expf(m - mn);
            const float e = __expf(s - mn);
            lsum = lsum * cc + e;
            acc.x = acc.x * cc + e * v4.x;
            acc.y = acc.y * cc + e * v4.y;
            acc.z = acc.z * cc + e * v4.z;
            acc.w = acc.w * cc + e * v4.w;
            m = mn;
        }
    };
    // 8-warp flash merge of partials in scratch -> normalized result in mo
    auto mergeFlash = [&]() {
        const int ln = tid;  // tid < 32
        float M = m_s[ln];
        #pragma unroll
        for (int w = 1; w < NW; ++w) M = fmaxf(M, m_s[w * 32 + ln]);
        float L = 0.f, ax = 0.f, ay = 0.f, az = 0.f, aw = 0.f;
        #pragma unroll
        for (int w = 0; w < NW; ++w) {
            const float cc = __expf(m_s[w * 32 + ln] - M);
            L += l_s[w * 32 + ln] * cc;
            const float4 a = a_s[w * 32 + ln];
            ax += a.x * cc; ay += a.y * cc; az += a.z * cc; aw += a.w * cc;
        }
        const float inv = 1.0f / L;
        mo[4 * ln + 0] = ax * inv;
        mo[4 * ln + 1] = ay * inv;
        mo[4 * ln + 2] = az * inv;
        mo[4 * ln + 3] = aw * inv;
    };

    // ==================== Layer 0 ====================
    stageKV(0, wid, rw);
    stageKV(0, wid + NW, rw + CH * 256);
    {
        const float4 q4 = *(const float4*)(qs + loff);
        float m = -1e30f, lsum = 0.0f;
        float4 acc = zero4();
        int it = 0;
        for (int c = wid; c < nch; c += NW, ++it) {
            __pipeline_wait_prior(1);
            float* buf = rw + (it & 1) * (CH * 256);
            consumeKV(buf, c, q4, m, lsum, acc);
            stageKV(0, c + 2 * NW, buf);
        }
        __pipeline_wait_prior(0);
        __syncthreads();   // warp0 ring area dead -> scratch
        m_s[wid * 32 + lane] = m;
        l_s[wid * 32 + lane] = lsum;
        a_s[wid * 32 + lane] = acc;
    }
    __syncthreads();
    // OVERLAP: warps 1..7 stage layer-1 prologue during merge + matmul
    if (wid >= 1) {
        stageKV(1, wid, rw);
        stageKV(1, wid + NW, rw + CH * 256);
    }
    if (tid < 32) mergeFlash();
    __syncthreads();
    if (tid < D) {   // qs = mo @ W0.T + b0
        const float* Wr = W0_w + tid * D;
        float a2 = W0_b[tid];
        #pragma unroll 8
        for (int d = 0; d < D; ++d) a2 = fmaf(mo[d], Wr[d], a2);
        qs[tid] = a2;
    }
    __syncthreads();
    if (wid == 0) {  // scratch dead now
        stageKV(1, 0, rw);
        stageKV(1, NW, rw + CH * 256);
    }

    // ==================== Layer 1 ====================
    {
        const float4 q4 = *(const float4*)(qs + loff);
        float m = -1e30f, lsum = 0.0f;
        float4 acc = zero4();
        int it = 0;
        for (int c = wid; c < nch; c += NW, ++it) {
            __pipeline_wait_prior(1);
            float* buf = rw + (it & 1) * (CH * 256);
            consumeKV(buf, c, q4, m, lsum, acc);
            stageKV(1, c + 2 * NW, buf);
        }
        __pipeline_wait_prior(0);
        __syncthreads();
        m_s[wid * 32 + lane] = m;
        l_s[wid * 32 + lane] = lsum;
        a_s[wid * 32 + lane] = acc;
    }
    __syncthreads();
    // OVERLAP: warps 1..7 stage layer-2 prologue during merge + 2 matmuls
    if (wid >= 1) {
        stageK2(wid, rw);
        stageK2(wid + NW, rw + CH2 * 128);
    }
    if (tid < 32) mergeFlash();
    __syncthreads();
    if (tid < D) {   // qs = mo @ W0.T + b0
        const float* Wr = W0_w + tid * D;
        float a2 = W0_b[tid];
        #pragma unroll 8
        for (int d = 0; d < D; ++d) a2 = fmaf(mo[d], Wr[d], a2);
        qs[tid] = a2;
    }
    __syncthreads();
    if (tid < D) {   // mo = qs @ Wq.T + bq   (q_final)
        const float* Wr = Wq_w + tid * D;
        float a2 = Wq_b[tid];
        #pragma unroll 8
        for (int d = 0; d < D; ++d) a2 = fmaf(qs[d], Wr[d], a2);
        mo[tid] = a2;
    }
    __syncthreads();
    if (wid == 0) {
        stageK2(0, rw);
        stageK2(NW, rw + CH2 * 128);
    }

    // ==================== Layer 2: 1-head, clip=10 ====================
    {
        const float4 q4 = *(const float4*)(mo + loff);
        float m = -1e30f, lsum = 0.0f;
        int it = 0;
        for (int c = wid; c < nch2; c += NW, ++it) {
            __pipeline_wait_prior(1);
            float* buf = rw + (it & 1) * (CH2 * 128);
            #pragma unroll
            for (int j = 0; j < CH2; ++j) {
                const int i = c * CH2 + j;
                const float4 k4 = *(const float4*)(buf + j * 128 + loff);
                float s = k4.x * q4.x + k4.y * q4.y + k4.z * q4.z + k4.w * q4.w;
                #pragma unroll
                for (int d = 1; d < 32; d <<= 1)
                    s += __shfl_xor_sync(0xffffffffu, s, d);
                s *= 0.08838834764831845f;   // 1/sqrt(128)
                s = 10.0f * (1.0f - __fdividef(2.0f, __expf(2.0f * s) + 1.0f));  // 10*tanh
                if (i < cnt) {
                    if (lane == 0) ss[i] = s;
                } else s = NEG;
                const float mn = fmaxf(m, s);
                lsum = lsum * __expf(m - mn) + __expf(s - mn);
                m = mn;
            }
            stageK2(c + 2 * NW, buf);
        }
        __pipeline_wait_prior(0);
        __syncthreads();
        if (lane == 0) { m_s[wid * 32] = m; l_s[wid * 32] = lsum; }
    }
    __syncthreads();
    if (tid == 0) {
        float M = m_s[0];
        #pragma unroll
        for (int w = 1; w < NW; ++w) M = fmaxf(M, m_s[w * 32]);
        float L = 0.f;
        #pragma unroll
        for (int w = 0; w < NW; ++w) L += l_s[w * 32] * __expf(m_s[w * 32] - M);
        M2s = M;
        L2s = 1.0f / L;
    }
    __syncthreads();

    // epilogue: zero the row, then scatter normalized weights from smem
    {
        const float M = M2s, Li = L2s;
        float* orow = out + (size_t)b * NN;
        for (int n = tid; n < NN; n += 256) orow[n] = 0.0f;
        __syncthreads();
        for (int i = tid; i < cnt; i += 256)
            orow[nlist[i]] = __expf(ss[i] - M) * Li;
    }
}

extern "C" void kernel_launch(void* const* d_in, const int* in_sizes, int n_in,
                              void* d_out, int out_size) {
    const float* query = (const float*)d_in[0];
    const float* K_att = (const float*)d_in[1];
    const float* V_att = (const float*)d_in[2];
    const int*   mask  = (const int*)d_in[3];
    const float* W0_w  = (const float*)d_in[4];
    const float* W0_b  = (const float*)d_in[5];
    const float* Wq_w  = (const float*)d_in[6];
    const float* Wq_b  = (const float*)d_in[7];
    float* out = (float*)d_out;

    decoder_fused_kernel<<<512, 256>>>(query, K_att, V_att, mask,
                                       W0_w, W0_b, Wq_w, Wq_b, out);
}